// round 2
// baseline (speedup 1.0000x reference)
#include <cuda_runtime.h>
#include <cuda_bf16.h>

// Soft cross-entropy: mean over n tokens of  mask * (logsumexp(x) * sum(t) - dot(t, x))
// n = 131072 rows, K = 256 classes (fast path), fp32, scalar output.
//
// Strategy: one warp per row. Each lane holds 8 classes via two float4 loads
// (perfectly coalesced 512B segments). Warp-shuffle reductions for max and the
// fused (expsum, dot, tsum). Deterministic two-pass reduction: per-block
// partials in a __device__ array, then a single-block final reduce into d_out.

#define MAX_PART_BLOCKS 16384

__device__ float g_partial[MAX_PART_BLOCKS];

__device__ __forceinline__ float warp_max(float v) {
#pragma unroll
    for (int off = 16; off; off >>= 1)
        v = fmaxf(v, __shfl_xor_sync(0xffffffffu, v, off));
    return v;
}

// Fast path: K == 256
__global__ void __launch_bounds__(256, 8)
sce_rows_k256(const float* __restrict__ in, const float* __restrict__ tg,
              const float* __restrict__ mask, int n) {
    const int warp = threadIdx.x >> 5;
    const int lane = threadIdx.x & 31;
    const int warps_per_grid = gridDim.x * 8;

    float acc = 0.0f;
    for (int row = blockIdx.x * 8 + warp; row < n; row += warps_per_grid) {
        const float4* __restrict__ xin = reinterpret_cast<const float4*>(in + (size_t)row * 256);
        const float4* __restrict__ xtg = reinterpret_cast<const float4*>(tg + (size_t)row * 256);
        // 2x float4 per lane: lanes 0..31 cover floats [0,128), then [128,256)
        float4 a0 = xin[lane];
        float4 a1 = xin[lane + 32];
        float4 b0 = xtg[lane];
        float4 b1 = xtg[lane + 32];

        float m = fmaxf(fmaxf(fmaxf(a0.x, a0.y), fmaxf(a0.z, a0.w)),
                        fmaxf(fmaxf(a1.x, a1.y), fmaxf(a1.z, a1.w)));
        m = warp_max(m);

        float s = __expf(a0.x - m) + __expf(a0.y - m) + __expf(a0.z - m) + __expf(a0.w - m)
                + __expf(a1.x - m) + __expf(a1.y - m) + __expf(a1.z - m) + __expf(a1.w - m);

        float dot = a0.x * b0.x;
        dot = fmaf(a0.y, b0.y, dot);
        dot = fmaf(a0.z, b0.z, dot);
        dot = fmaf(a0.w, b0.w, dot);
        dot = fmaf(a1.x, b1.x, dot);
        dot = fmaf(a1.y, b1.y, dot);
        dot = fmaf(a1.z, b1.z, dot);
        dot = fmaf(a1.w, b1.w, dot);

        float ts = (b0.x + b0.y) + (b0.z + b0.w) + (b1.x + b1.y) + (b1.z + b1.w);

#pragma unroll
        for (int off = 16; off; off >>= 1) {
            s   += __shfl_xor_sync(0xffffffffu, s,   off);
            dot += __shfl_xor_sync(0xffffffffu, dot, off);
            ts  += __shfl_xor_sync(0xffffffffu, ts,  off);
        }
        // every lane has the full reductions; lane 0's value is what's stored
        acc += ((m + __logf(s)) * ts - dot) * mask[row];
    }

    __shared__ float sm[8];
    if (lane == 0) sm[warp] = acc;
    __syncthreads();
    if (threadIdx.x == 0) {
        float blk = 0.0f;
#pragma unroll
        for (int i = 0; i < 8; i++) blk += sm[i];
        g_partial[blockIdx.x] = blk;
    }
}

// Generic path: any K (warp per row, strided lanes)
__global__ void __launch_bounds__(256, 8)
sce_rows_generic(const float* __restrict__ in, const float* __restrict__ tg,
                 const float* __restrict__ mask, int n, int K) {
    const int warp = threadIdx.x >> 5;
    const int lane = threadIdx.x & 31;
    const int warps_per_grid = gridDim.x * 8;

    float acc = 0.0f;
    for (int row = blockIdx.x * 8 + warp; row < n; row += warps_per_grid) {
        const float* __restrict__ xin = in + (size_t)row * K;
        const float* __restrict__ xtg = tg + (size_t)row * K;

        float m = -__FLT_MAX__;
        for (int j = lane; j < K; j += 32) m = fmaxf(m, xin[j]);
        m = warp_max(m);

        float s = 0.0f, dot = 0.0f, ts = 0.0f;
        for (int j = lane; j < K; j += 32) {
            float x = xin[j], t = xtg[j];
            s += __expf(x - m);
            dot = fmaf(x, t, dot);
            ts += t;
        }
#pragma unroll
        for (int off = 16; off; off >>= 1) {
            s   += __shfl_xor_sync(0xffffffffu, s,   off);
            dot += __shfl_xor_sync(0xffffffffu, dot, off);
            ts  += __shfl_xor_sync(0xffffffffu, ts,  off);
        }
        acc += ((m + __logf(s)) * ts - dot) * mask[row];
    }

    __shared__ float sm[8];
    if (lane == 0) sm[warp] = acc;
    __syncthreads();
    if (threadIdx.x == 0) {
        float blk = 0.0f;
#pragma unroll
        for (int i = 0; i < 8; i++) blk += sm[i];
        g_partial[blockIdx.x] = blk;
    }
}

__global__ void sce_final(float* __restrict__ out, int nblocks, float inv_n) {
    __shared__ float sm[512];
    float acc = 0.0f;
    for (int i = threadIdx.x; i < nblocks; i += 512) acc += g_partial[i];
    sm[threadIdx.x] = acc;
    __syncthreads();
#pragma unroll
    for (int s = 256; s > 0; s >>= 1) {
        if (threadIdx.x < s) sm[threadIdx.x] += sm[threadIdx.x + s];
        __syncthreads();
    }
    if (threadIdx.x == 0) out[0] = sm[0] * inv_n;
}

extern "C" void kernel_launch(void* const* d_in, const int* in_sizes, int n_in,
                              void* d_out, int out_size) {
    const float* in   = (const float*)d_in[0];
    const float* tg   = (const float*)d_in[1];
    const float* mask = (const float*)d_in[2];
    float* out = (float*)d_out;

    const int n = in_sizes[2];              // B*S rows
    const int K = in_sizes[0] / n;          // classes per row

    int blocks = (n + 7) / 8;
    if (blocks > MAX_PART_BLOCKS) blocks = MAX_PART_BLOCKS;

    if (K == 256) {
        sce_rows_k256<<<blocks, 256>>>(in, tg, mask, n);
    } else {
        sce_rows_generic<<<blocks, 256>>>(in, tg, mask, n, K);
    }
    sce_final<<<1, 512>>>(out, blocks, 1.0f / (float)n);
}